// round 13
// baseline (speedup 1.0000x reference)
#include <cuda_runtime.h>
#include <cstdint>

#define GROUPS  2048
#define MM      64
#define CC      128
#define TOK     8192
#define RK      8
#define RRR     512
#define MASKN   524288

// Fragment-permuted operand storage:
//  A (T1, 2048x512): tile (mt,ks), stored [mt][ks][128]; element (tr,tc)
//      at lane=(tr&7)*4+(tc&3), reg=(tr>>3)+((tc>>2)<<1)
//  B (W4, 512x512):  tile (nt,ks), stored [nt][ks][64];  element (n,k)
//      at lane=(n&7)*4+(k&3),  reg=k>>2
__device__ float g_s  [(size_t)GROUPS * TOK];  // 64 MB group sums
__device__ float g_t1h[(size_t)GROUPS * RRR];  // 4 MB  T1 hi (permuted)
__device__ float g_t1l[(size_t)GROUPS * RRR];  // 4 MB  T1 lo (permuted)
__device__ float g_u2 [(size_t)GROUPS * RRR];  // 4 MB
__device__ float g_w4h[RRR * RRR];             // 1 MB  W4 hi (permuted)
__device__ float g_w4l[RRR * RRR];             // 1 MB  W4 lo (permuted)
__device__ int   g_flags[2];                   // [ge2, odd]

__device__ __forceinline__ void tf32_split(float v, float& hi, float& lo)
{
    unsigned hb, lb;
    asm("cvt.rna.tf32.f32 %0, %1;" : "=r"(hb) : "f"(v));
    hi = __uint_as_float(hb);
    float r = v - hi;
    asm("cvt.rna.tf32.f32 %0, %1;" : "=r"(lb) : "f"(r));
    lo = __uint_as_float(lb);
}

__device__ __forceinline__ size_t a_perm_idx(int gr, int c)
{
    int mt = gr >> 4, tr = gr & 15;
    int ks = c >> 3,  tc = c & 7;
    int lane = (tr & 7) * 4 + (tc & 3);
    int reg  = (tr >> 3) + ((tc >> 2) << 1);
    return (size_t)(mt * 64 + ks) * 128 + lane * 4 + reg;
}
__device__ __forceinline__ size_t b_perm_idx(int n, int k)
{
    int nt = n >> 3, gid = n & 7;
    int ks = k >> 3, kc = k & 7;
    int lane = gid * 4 + (kc & 3);
    int reg  = kc >> 2;
    return (size_t)(nt * 64 + ks) * 64 + lane * 2 + reg;
}

// ---------------------------------------------------------------------------
// Combined fold + mask-scan kernel. blocks 0..63: fold W4; 64..127: scan mask.
// ---------------------------------------------------------------------------
__global__ void __launch_bounds__(256) fold_and_scan(
    const float* __restrict__ core,
    const float* __restrict__ of0, const float* __restrict__ of1,
    const float* __restrict__ if0, const float* __restrict__ if1,
    const unsigned char* __restrict__ mask)
{
    const int tid = threadIdx.x;

    if (blockIdx.x >= 64) {
        // ---- mask dtype scan (64 blocks) ----
        const uint4* p = (const uint4*)mask;
        unsigned acc = 0;
        int i = (blockIdx.x - 64) * 256 + tid;
        for (; i < MASKN / 16; i += 64 * 256) {
            uint4 v = p[i];
            acc |= (v.x | v.y | v.z | v.w);
        }
        __shared__ unsigned sacc;
        if (tid == 0) sacc = 0;
        __syncthreads();
        #pragma unroll
        for (int off = 16; off >= 1; off >>= 1)
            acc |= __shfl_xor_sync(0xffffffffu, acc, off);
        if ((tid & 31) == 0) atomicOr(&sacc, acc);
        __syncthreads();
        if (tid == 0) {
            unsigned a = sacc;
            if (a & 0xFEFEFEFEu) atomicOr(&g_flags[0], 1);
            if (a & 0xFFFFFF00u) atomicOr(&g_flags[1], 1);
        }
        return;
    }

    // ---- fold (64 blocks), one (C,F) pair per block ----
    __shared__ float bufA[4096], bufB[4096];
    __shared__ float sf[4][64];
    const int C = blockIdx.x >> 3, F = blockIdx.x & 7;

    if (tid < 64)       sf[0][tid]       = of0[tid];
    else if (tid < 128) sf[1][tid - 64]  = of1[tid - 64];
    else if (tid < 192) sf[2][tid - 128] = if0[tid - 128];
    else                sf[3][tid - 192] = if1[tid - 192];

    #pragma unroll
    for (int i = tid; i < 4096; i += 256) {
        int A = i >> 9, B = (i >> 6) & 7, D = (i >> 3) & 7, E = i & 7;
        bufA[i] = core[A * 32768 + B * 4096 + C * 512 + D * 64 + E * 8 + F];
    }
    __syncthreads();
    #pragma unroll
    for (int i = tid; i < 4096; i += 256) {   // M1[A,B,D,d] = sum_E K * if1[d,E]
        int ABD = i >> 3, d = i & 7;
        float acc = 0.f;
        #pragma unroll
        for (int E = 0; E < 8; E++) acc += bufA[ABD * 8 + E] * sf[3][d * 8 + E];
        bufB[i] = acc;
    }
    __syncthreads();
    #pragma unroll
    for (int i = tid; i < 4096; i += 256) {   // M2[A,B,d,a] = sum_D M1 * if0[a,D]
        int AB = i >> 6, d = (i >> 3) & 7, a = i & 7;
        float acc = 0.f;
        #pragma unroll
        for (int D = 0; D < 8; D++) acc += bufB[(AB * 8 + D) * 8 + d] * sf[2][a * 8 + D];
        bufA[i] = acc;
    }
    __syncthreads();
    #pragma unroll
    for (int i = tid; i < 4096; i += 256) {   // M3[B,d,a,o] = sum_A M2 * of0[o,A]
        int B = i >> 9, d = (i >> 6) & 7, a = (i >> 3) & 7, o = i & 7;
        float acc = 0.f;
        #pragma unroll
        for (int A = 0; A < 8; A++)
            acc += bufA[((A * 8 + B) * 8 + d) * 8 + a] * sf[0][o * 8 + A];
        bufB[i] = acc;
    }
    __syncthreads();
    #pragma unroll
    for (int i = tid; i < 4096; i += 256) {   // W4 = sum_B M3 * of1[p,B]
        int o = i >> 9, p = (i >> 6) & 7, a = (i >> 3) & 7, d = i & 7;
        float acc = 0.f;
        #pragma unroll
        for (int B = 0; B < 8; B++)
            acc += bufB[((B * 8 + d) * 8 + a) * 8 + o] * sf[1][p * 8 + B];
        float hi, lo;
        tf32_split(acc, hi, lo);
        int n = (o * 8 + p) * 8 + C;
        int k = a * 64 + d * 8 + F;
        size_t idx = b_perm_idx(n, k);
        g_w4h[idx] = hi;
        g_w4l[idx] = lo;
    }
}

// ---------------------------------------------------------------------------
// Kernel 1: grid 4096 (half-group per block): s -> scratch, T1 hi/lo permuted.
// ---------------------------------------------------------------------------
__global__ void __launch_bounds__(256) k1_reduce_project(
    const float* __restrict__ x,
    const float* __restrict__ in_f2)   // (128,8)
{
    __shared__ __align__(16) float s[32 * 132];
    __shared__ __align__(16) float f2q[8 * 132];   // [F][e]
    __shared__ __align__(16) float part[32 * 68];  // p[m][c][F] = m*68+c*8+F

    const int tid = threadIdx.x;
    const int g = blockIdx.x >> 1, h = blockIdx.x & 1;
    const size_t base = (size_t)g * (4 * TOK) + h * 4096;

    #pragma unroll
    for (int i = tid; i < CC * RK; i += 256) {
        int e = i >> 3, F = i & 7;
        f2q[F * 132 + e] = in_f2[i];
    }

    const float4* xb = (const float4*)(x + base);
    float4*       sg = (float4*)(g_s + (size_t)g * TOK + h * 4096);
    #pragma unroll
    for (int it = 0; it < 4; it++) {
        int i = tid + it * 256;
        float4 v0 = __ldcs(&xb[i]);
        float4 v1 = __ldcs(&xb[i + 2048]);
        float4 v2 = __ldcs(&xb[i + 4096]);
        float4 v3 = __ldcs(&xb[i + 6144]);
        float4 r;
        r.x = (v0.x + v1.x) + (v2.x + v3.x);
        r.y = (v0.y + v1.y) + (v2.y + v3.y);
        r.z = (v0.z + v1.z) + (v2.z + v3.z);
        r.w = (v0.w + v1.w) + (v2.w + v3.w);
        sg[i] = r;
        int m = i >> 5;
        int e = (i & 31) << 2;
        *(float4*)&s[m * 132 + e] = r;
    }
    __syncthreads();

    // phase 2a: partials. m = tid&31 (lane), c = tid>>5 (warp-uniform chunk)
    {
        int m = tid & 31;
        int c = tid >> 5;
        const float4* s4 = (const float4*)&s[m * 132 + c * 16];
        float acc[8];
        #pragma unroll
        for (int F = 0; F < 8; F++) acc[F] = 0.f;
        #pragma unroll
        for (int q = 0; q < 4; q++) {
            float4 a = s4[q];                       // row read, conflict-free
            #pragma unroll
            for (int F = 0; F < 8; F++) {
                float4 b = *(const float4*)&f2q[F * 132 + c * 16 + q * 4]; // broadcast
                acc[F] += a.x * b.x + a.y * b.y + a.z * b.z + a.w * b.w;
            }
        }
        #pragma unroll
        for (int F = 0; F < 8; F += 4)
            *(float4*)&part[m * 68 + c * 8 + F] = make_float4(acc[F], acc[F+1], acc[F+2], acc[F+3]);
    }
    __syncthreads();

    // phase 2b: reduce 8 chunks -> t1[m,F], tf32-split, permuted store
    {
        int m = tid >> 3, F = tid & 7;
        float acc = 0.f;
        #pragma unroll
        for (int c = 0; c < 8; c++)
            acc += part[m * 68 + c * 8 + F];
        float hi, lo;
        tf32_split(acc, hi, lo);
        size_t idx = a_perm_idx(g, (h * 32 + m) * 8 + F);
        g_t1h[idx] = hi;
        g_t1l[idx] = lo;
    }
}

// ---------------------------------------------------------------------------
// Kernel 2: U2 = T1 @ W4^T — cp.async 3-stage pipeline, BK=64 (2 k8-slabs per
// stage), ONE __syncthreads per iteration. BM=64 BN=64, 3xTF32, grid (32,8).
// ---------------------------------------------------------------------------
__device__ __forceinline__ void k2_issue_slab(float* sA, float* sB, int ks,
                                              int bm, int bn, int tid)
{
    int half = tid >> 7, r = tid & 127;
    {   // A: 4 m-tiles x 128 floats x {hi,lo}
        int mt = r >> 5, off = (r & 31) * 4;
        const float* src = (half ? g_t1l : g_t1h)
                         + ((size_t)((bm >> 4) + mt) * 64 + ks) * 128 + off;
        unsigned dst = (unsigned)__cvta_generic_to_shared(&sA[half * 512 + mt * 128 + off]);
        asm volatile("cp.async.cg.shared.global [%0], [%1], 16;" :: "r"(dst), "l"(src));
    }
    {   // B: 8 n-tiles x 64 floats x {hi,lo}
        int nt = r >> 4, off = (r & 15) * 4;
        const float* src = (half ? g_w4l : g_w4h)
                         + ((size_t)((bn >> 3) + nt) * 64 + ks) * 64 + off;
        unsigned dst = (unsigned)__cvta_generic_to_shared(&sB[half * 512 + nt * 64 + off]);
        asm volatile("cp.async.cg.shared.global [%0], [%1], 16;" :: "r"(dst), "l"(src));
    }
}

__global__ void __launch_bounds__(256) k2_core_gemm()
{
    __shared__ __align__(16) float sA[3][2048];
    __shared__ __align__(16) float sB[3][2048];

    const int tid  = threadIdx.x;
    const int lane = tid & 31;
    const int wid  = tid >> 5;
    const int wm   = wid >> 2;          // 0..1
    const int wn   = wid & 3;           // 0..3
    const int gid  = lane >> 2;
    const int tig  = lane & 3;
    const int bm   = blockIdx.x * 64;
    const int bn   = blockIdx.y * 64;

    float acc[2][2][4];
    #pragma unroll
    for (int mi = 0; mi < 2; mi++)
        #pragma unroll
        for (int ni = 0; ni < 2; ni++)
            #pragma unroll
            for (int r = 0; r < 4; r++) acc[mi][ni][r] = 0.f;

    #pragma unroll
    for (int st = 0; st < 2; st++) {
        k2_issue_slab(&sA[st][0],    &sB[st][0],    st * 2,     bm, bn, tid);
        k2_issue_slab(&sA[st][1024], &sB[st][1024], st * 2 + 1, bm, bn, tid);
        asm volatile("cp.async.commit_group;" ::: "memory");
    }

    int st = 0;
    for (int it = 0; it < 32; it++) {
        asm volatile("cp.async.wait_group 1;" ::: "memory");
        __syncthreads();
        #pragma unroll
        for (int s = 0; s < 2; s++) {
            uint4 ah[2], al[2];
            uint2 bh[2], bl[2];
            #pragma unroll
            for (int mi = 0; mi < 2; mi++) {
                ah[mi] = *(const uint4*)&sA[st][s * 1024 + (wm * 2 + mi) * 128 + lane * 4];
                al[mi] = *(const uint4*)&sA[st][s * 1024 + 512 + (wm * 2 + mi) * 128 + lane * 4];
            }
            #pragma unroll
            for (int ni = 0; ni < 2; ni++) {
                bh[ni] = *(const uint2*)&sB[st][s * 1024 + (wn * 2 + ni) * 64 + lane * 2];
                bl[ni] = *(const uint2*)&sB[st][s * 1024 + 512 + (wn * 2 + ni) * 64 + lane * 2];
            }
            if (s == 0) {
                if (it < 30) {
                    int nst = st + 2; if (nst >= 3) nst -= 3;
                    k2_issue_slab(&sA[nst][0],    &sB[nst][0],    (it + 2) * 2,     bm, bn, tid);
                    k2_issue_slab(&sA[nst][1024], &sB[nst][1024], (it + 2) * 2 + 1, bm, bn, tid);
                }
                asm volatile("cp.async.commit_group;" ::: "memory");
            }
            #pragma unroll
            for (int mi = 0; mi < 2; mi++)
                #pragma unroll
                for (int ni = 0; ni < 2; ni++) {
                    float* c = acc[mi][ni];
                    asm volatile(
                        "mma.sync.aligned.m16n8k8.row.col.f32.tf32.tf32.f32 "
                        "{%0,%1,%2,%3}, {%4,%5,%6,%7}, {%8,%9}, {%0,%1,%2,%3};"
                        : "+f"(c[0]), "+f"(c[1]), "+f"(c[2]), "+f"(c[3])
                        : "r"(ah[mi].x), "r"(ah[mi].y), "r"(ah[mi].z), "r"(ah[mi].w),
                          "r"(bh[ni].x), "r"(bh[ni].y));
                    asm volatile(
                        "mma.sync.aligned.m16n8k8.row.col.f32.tf32.tf32.f32 "
                        "{%0,%1,%2,%3}, {%4,%5,%6,%7}, {%8,%9}, {%0,%1,%2,%3};"
                        : "+f"(c[0]), "+f"(c[1]), "+f"(c[2]), "+f"(c[3])
                        : "r"(al[mi].x), "r"(al[mi].y), "r"(al[mi].z), "r"(al[mi].w),
                          "r"(bh[ni].x), "r"(bh[ni].y));
                    asm volatile(
                        "mma.sync.aligned.m16n8k8.row.col.f32.tf32.tf32.f32 "
                        "{%0,%1,%2,%3}, {%4,%5,%6,%7}, {%8,%9}, {%0,%1,%2,%3};"
                        : "+f"(c[0]), "+f"(c[1]), "+f"(c[2]), "+f"(c[3])
                        : "r"(ah[mi].x), "r"(ah[mi].y), "r"(ah[mi].z), "r"(ah[mi].w),
                          "r"(bl[ni].x), "r"(bl[ni].y));
                }
        }
        if (++st == 3) st = 0;
    }

    #pragma unroll
    for (int mi = 0; mi < 2; mi++)
        #pragma unroll
        for (int ni = 0; ni < 2; ni++) {
            int row0 = bm + wm * 32 + mi * 16 + gid;
            int col  = bn + wn * 16 + ni * 8 + tig * 2;
            float* c = acc[mi][ni];
            *(float2*)&g_u2[(size_t)row0 * RRR + col]       = make_float2(c[0], c[1]);
            *(float2*)&g_u2[(size_t)(row0 + 8) * RRR + col] = make_float2(c[2], c[3]);
        }
}

// ---------------------------------------------------------------------------
// Kernel 3: grid 4096. out = (u2·f2^T + s) * invw.
// All 4 streaming LDGs issue at kernel ENTRY (before the smem prologue) so the
// DRAM latency overlaps u2/f2/mask staging; compute phase then consumes regs.
// ---------------------------------------------------------------------------
__global__ void __launch_bounds__(256) k3_stream(
    const float* __restrict__ out_f2,
    const void*  __restrict__ maskp,
    float* __restrict__ out)
{
    __shared__ float f2t[RK * CC];
    __shared__ float u2s[256];
    __shared__ float invw[32];

    const int tid = threadIdx.x;
    const int g = blockIdx.x >> 1, h = blockIdx.x & 1;

    // ---- issue all streaming loads FIRST (independent of smem) ----
    const float4* sg = (const float4*)(g_s + (size_t)g * TOK + h * 4096);
    float4 sv[4];
    #pragma unroll
    for (int it = 0; it < 4; it++)
        sv[it] = __ldcs(&sg[tid + it * 256]);

    // ---- prologue overlaps the loads above ----
    if (tid < 64)
        ((float4*)u2s)[tid] = ((const float4*)(g_u2 + (size_t)g * RRR + h * 256))[tid];
    #pragma unroll
    for (int i = tid; i < RK * CC; i += 256) {
        int q = i >> 3, Cr = i & 7;
        f2t[Cr * CC + q] = out_f2[i];
    }
    if (tid < 32) {
        int ge2 = g_flags[0], odd = g_flags[1];
        int m = h * 32 + tid;
        int w;
        if (ge2) {
            const float* mf = (const float*)maskp + (size_t)g * 256;
            w = (mf[m] != 0.f ? 0 : 1) + (mf[m + 64] != 0.f ? 0 : 1)
              + (mf[m + 128] != 0.f ? 0 : 1) + (mf[m + 192] != 0.f ? 0 : 1);
        } else if (odd) {
            const unsigned char* mb = (const unsigned char*)maskp + (size_t)g * 256;
            w = (mb[m] ? 0 : 1) + (mb[m + 64] ? 0 : 1)
              + (mb[m + 128] ? 0 : 1) + (mb[m + 192] ? 0 : 1);
        } else {
            const int* mi = (const int*)maskp + (size_t)g * 256;
            w = (mi[m] ? 0 : 1) + (mi[m + 64] ? 0 : 1)
              + (mi[m + 128] ? 0 : 1) + (mi[m + 192] ? 0 : 1);
        }
        invw[tid] = (w > 0) ? 1.0f / ((float)w + 1e-10f) : 0.0f;
    }
    __syncthreads();

    const int q0 = (tid & 31) << 2;
    float4 rf2[8];
    #pragma unroll
    for (int Cr = 0; Cr < 8; Cr++)
        rf2[Cr] = *(const float4*)&f2t[Cr * CC + q0];

    float4* og = (float4*)(out + (size_t)g * TOK + h * 4096);
    #pragma unroll
    for (int it = 0; it < 4; it++) {
        int i  = tid + it * 256;
        int m  = i >> 5;
        float r0 = 0.f, r1 = 0.f, r2 = 0.f, r3 = 0.f;
        #pragma unroll
        for (int Cr = 0; Cr < 8; Cr++) {
            float u = u2s[m * 8 + Cr];          // warp-uniform broadcast
            float4 f = rf2[Cr];
            r0 += u * f.x; r1 += u * f.y; r2 += u * f.z; r3 += u * f.w;
        }
        float iw = invw[m];
        float4 ov;
        ov.x = (r0 + sv[it].x) * iw;
        ov.y = (r1 + sv[it].y) * iw;
        ov.z = (r2 + sv[it].z) * iw;
        ov.w = (r3 + sv[it].w) * iw;
        __stcs(&og[i], ov);
    }
}

// ---------------------------------------------------------------------------
// inputs: 0:x 1:core 2:out_f0 3:out_f1 4:out_f2 5:in_f0 6:in_f1 7:in_f2 8:mask
// ---------------------------------------------------------------------------
extern "C" void kernel_launch(void* const* d_in, const int* in_sizes, int n_in,
                              void* d_out, int out_size)
{
    const float* x      = (const float*)d_in[0];
    const float* core   = (const float*)d_in[1];
    const float* out_f0 = (const float*)d_in[2];
    const float* out_f1 = (const float*)d_in[3];
    const float* out_f2 = (const float*)d_in[4];
    const float* in_f0  = (const float*)d_in[5];
    const float* in_f1  = (const float*)d_in[6];
    const float* in_f2  = (const float*)d_in[7];
    float* out = (float*)d_out;

    void* flags_ptr = nullptr;
    cudaGetSymbolAddress(&flags_ptr, g_flags);
    cudaMemsetAsync(flags_ptr, 0, 2 * sizeof(int));

    fold_and_scan<<<128, 256>>>(core, out_f0, out_f1, in_f0, in_f1,
                                (const unsigned char*)d_in[8]);
    k1_reduce_project<<<2 * GROUPS, 256>>>(x, in_f2);
    dim3 g2(GROUPS / 64, RRR / 64);
    k2_core_gemm<<<g2, 256>>>();
    k3_stream<<<2 * GROUPS, 256>>>(out_f2, d_in[8], out);
}

// round 14
// speedup vs baseline: 1.0653x; 1.0653x over previous
#include <cuda_runtime.h>
#include <cstdint>

#define GROUPS  2048
#define MM      64
#define CC      128
#define TOK     8192
#define RK      8
#define RRR     512
#define MASKN   524288

// Fragment-permuted operand storage:
//  A (T1, 2048x512): tile (mt,ks), stored [mt][ks][128]; element (tr,tc)
//      at lane=(tr&7)*4+(tc&3), reg=(tr>>3)+((tc>>2)<<1)
//  B (W4, 512x512):  tile (nt,ks), stored [nt][ks][64];  element (n,k)
//      at lane=(n&7)*4+(k&3),  reg=k>>2
__device__ float g_s  [(size_t)GROUPS * TOK];  // 64 MB group sums
__device__ float g_t1h[(size_t)GROUPS * RRR];  // 4 MB  T1 hi (permuted)
__device__ float g_t1l[(size_t)GROUPS * RRR];  // 4 MB  T1 lo (permuted)
__device__ float g_u2 [(size_t)GROUPS * RRR];  // 4 MB
__device__ float g_w4h[RRR * RRR];             // 1 MB  W4 hi (permuted)
__device__ float g_w4l[RRR * RRR];             // 1 MB  W4 lo (permuted)
__device__ int   g_flags[2];                   // [ge2, odd]

__device__ __forceinline__ void tf32_split(float v, float& hi, float& lo)
{
    unsigned hb, lb;
    asm("cvt.rna.tf32.f32 %0, %1;" : "=r"(hb) : "f"(v));
    hi = __uint_as_float(hb);
    float r = v - hi;
    asm("cvt.rna.tf32.f32 %0, %1;" : "=r"(lb) : "f"(r));
    lo = __uint_as_float(lb);
}

__device__ __forceinline__ size_t a_perm_idx(int gr, int c)
{
    int mt = gr >> 4, tr = gr & 15;
    int ks = c >> 3,  tc = c & 7;
    int lane = (tr & 7) * 4 + (tc & 3);
    int reg  = (tr >> 3) + ((tc >> 2) << 1);
    return (size_t)(mt * 64 + ks) * 128 + lane * 4 + reg;
}
__device__ __forceinline__ size_t b_perm_idx(int n, int k)
{
    int nt = n >> 3, gid = n & 7;
    int ks = k >> 3, kc = k & 7;
    int lane = gid * 4 + (kc & 3);
    int reg  = kc >> 2;
    return (size_t)(nt * 64 + ks) * 64 + lane * 2 + reg;
}

// ---------------------------------------------------------------------------
// Combined fold + mask-scan kernel. blocks 0..63: fold W4; 64..127: scan mask.
// ---------------------------------------------------------------------------
__global__ void __launch_bounds__(256) fold_and_scan(
    const float* __restrict__ core,
    const float* __restrict__ of0, const float* __restrict__ of1,
    const float* __restrict__ if0, const float* __restrict__ if1,
    const unsigned char* __restrict__ mask)
{
    const int tid = threadIdx.x;

    if (blockIdx.x >= 64) {
        // ---- mask dtype scan (64 blocks) ----
        const uint4* p = (const uint4*)mask;
        unsigned acc = 0;
        int i = (blockIdx.x - 64) * 256 + tid;
        for (; i < MASKN / 16; i += 64 * 256) {
            uint4 v = p[i];
            acc |= (v.x | v.y | v.z | v.w);
        }
        __shared__ unsigned sacc;
        if (tid == 0) sacc = 0;
        __syncthreads();
        #pragma unroll
        for (int off = 16; off >= 1; off >>= 1)
            acc |= __shfl_xor_sync(0xffffffffu, acc, off);
        if ((tid & 31) == 0) atomicOr(&sacc, acc);
        __syncthreads();
        if (tid == 0) {
            unsigned a = sacc;
            if (a & 0xFEFEFEFEu) atomicOr(&g_flags[0], 1);
            if (a & 0xFFFFFF00u) atomicOr(&g_flags[1], 1);
        }
        return;
    }

    // ---- fold (64 blocks), one (C,F) pair per block ----
    __shared__ float bufA[4096], bufB[4096];
    __shared__ float sf[4][64];
    const int C = blockIdx.x >> 3, F = blockIdx.x & 7;

    if (tid < 64)       sf[0][tid]       = of0[tid];
    else if (tid < 128) sf[1][tid - 64]  = of1[tid - 64];
    else if (tid < 192) sf[2][tid - 128] = if0[tid - 128];
    else                sf[3][tid - 192] = if1[tid - 192];

    #pragma unroll
    for (int i = tid; i < 4096; i += 256) {
        int A = i >> 9, B = (i >> 6) & 7, D = (i >> 3) & 7, E = i & 7;
        bufA[i] = core[A * 32768 + B * 4096 + C * 512 + D * 64 + E * 8 + F];
    }
    __syncthreads();
    #pragma unroll
    for (int i = tid; i < 4096; i += 256) {   // M1[A,B,D,d] = sum_E K * if1[d,E]
        int ABD = i >> 3, d = i & 7;
        float acc = 0.f;
        #pragma unroll
        for (int E = 0; E < 8; E++) acc += bufA[ABD * 8 + E] * sf[3][d * 8 + E];
        bufB[i] = acc;
    }
    __syncthreads();
    #pragma unroll
    for (int i = tid; i < 4096; i += 256) {   // M2[A,B,d,a] = sum_D M1 * if0[a,D]
        int AB = i >> 6, d = (i >> 3) & 7, a = i & 7;
        float acc = 0.f;
        #pragma unroll
        for (int D = 0; D < 8; D++) acc += bufB[(AB * 8 + D) * 8 + d] * sf[2][a * 8 + D];
        bufA[i] = acc;
    }
    __syncthreads();
    #pragma unroll
    for (int i = tid; i < 4096; i += 256) {   // M3[B,d,a,o] = sum_A M2 * of0[o,A]
        int B = i >> 9, d = (i >> 6) & 7, a = (i >> 3) & 7, o = i & 7;
        float acc = 0.f;
        #pragma unroll
        for (int A = 0; A < 8; A++)
            acc += bufA[((A * 8 + B) * 8 + d) * 8 + a] * sf[0][o * 8 + A];
        bufB[i] = acc;
    }
    __syncthreads();
    #pragma unroll
    for (int i = tid; i < 4096; i += 256) {   // W4 = sum_B M3 * of1[p,B]
        int o = i >> 9, p = (i >> 6) & 7, a = (i >> 3) & 7, d = i & 7;
        float acc = 0.f;
        #pragma unroll
        for (int B = 0; B < 8; B++)
            acc += bufB[((B * 8 + d) * 8 + a) * 8 + o] * sf[1][p * 8 + B];
        float hi, lo;
        tf32_split(acc, hi, lo);
        int n = (o * 8 + p) * 8 + C;
        int k = a * 64 + d * 8 + F;
        size_t idx = b_perm_idx(n, k);
        g_w4h[idx] = hi;
        g_w4l[idx] = lo;
    }
}

// ---------------------------------------------------------------------------
// Kernel 1: grid 4096 (half-group per block): s -> scratch, T1 hi/lo permuted.
// ---------------------------------------------------------------------------
__global__ void __launch_bounds__(256) k1_reduce_project(
    const float* __restrict__ x,
    const float* __restrict__ in_f2)   // (128,8)
{
    __shared__ __align__(16) float s[32 * 132];
    __shared__ __align__(16) float f2q[8 * 132];   // [F][e]
    __shared__ __align__(16) float part[32 * 68];  // p[m][c][F] = m*68+c*8+F

    const int tid = threadIdx.x;
    const int g = blockIdx.x >> 1, h = blockIdx.x & 1;
    const size_t base = (size_t)g * (4 * TOK) + h * 4096;

    #pragma unroll
    for (int i = tid; i < CC * RK; i += 256) {
        int e = i >> 3, F = i & 7;
        f2q[F * 132 + e] = in_f2[i];
    }

    const float4* xb = (const float4*)(x + base);
    float4*       sg = (float4*)(g_s + (size_t)g * TOK + h * 4096);
    #pragma unroll
    for (int it = 0; it < 4; it++) {
        int i = tid + it * 256;
        float4 v0 = __ldcs(&xb[i]);
        float4 v1 = __ldcs(&xb[i + 2048]);
        float4 v2 = __ldcs(&xb[i + 4096]);
        float4 v3 = __ldcs(&xb[i + 6144]);
        float4 r;
        r.x = (v0.x + v1.x) + (v2.x + v3.x);
        r.y = (v0.y + v1.y) + (v2.y + v3.y);
        r.z = (v0.z + v1.z) + (v2.z + v3.z);
        r.w = (v0.w + v1.w) + (v2.w + v3.w);
        sg[i] = r;
        int m = i >> 5;
        int e = (i & 31) << 2;
        *(float4*)&s[m * 132 + e] = r;
    }
    __syncthreads();

    // phase 2a: partials. m = tid&31 (lane), c = tid>>5 (warp-uniform chunk)
    {
        int m = tid & 31;
        int c = tid >> 5;
        const float4* s4 = (const float4*)&s[m * 132 + c * 16];
        float acc[8];
        #pragma unroll
        for (int F = 0; F < 8; F++) acc[F] = 0.f;
        #pragma unroll
        for (int q = 0; q < 4; q++) {
            float4 a = s4[q];                       // row read, conflict-free
            #pragma unroll
            for (int F = 0; F < 8; F++) {
                float4 b = *(const float4*)&f2q[F * 132 + c * 16 + q * 4]; // broadcast
                acc[F] += a.x * b.x + a.y * b.y + a.z * b.z + a.w * b.w;
            }
        }
        #pragma unroll
        for (int F = 0; F < 8; F += 4)
            *(float4*)&part[m * 68 + c * 8 + F] = make_float4(acc[F], acc[F+1], acc[F+2], acc[F+3]);
    }
    __syncthreads();

    // phase 2b: reduce 8 chunks -> t1[m,F], tf32-split, permuted store
    {
        int m = tid >> 3, F = tid & 7;
        float acc = 0.f;
        #pragma unroll
        for (int c = 0; c < 8; c++)
            acc += part[m * 68 + c * 8 + F];
        float hi, lo;
        tf32_split(acc, hi, lo);
        size_t idx = a_perm_idx(g, (h * 32 + m) * 8 + F);
        g_t1h[idx] = hi;
        g_t1l[idx] = lo;
    }
}

// ---------------------------------------------------------------------------
// Kernel 2: U2 = T1 @ W4^T — cp.async 3-stage pipeline, BK=64 (2 k8-slabs per
// stage), ONE __syncthreads per iteration. BM=64 BN=64, 3xTF32, grid (32,8).
// ---------------------------------------------------------------------------
__device__ __forceinline__ void k2_issue_slab(float* sA, float* sB, int ks,
                                              int bm, int bn, int tid)
{
    int half = tid >> 7, r = tid & 127;
    {   // A: 4 m-tiles x 128 floats x {hi,lo}
        int mt = r >> 5, off = (r & 31) * 4;
        const float* src = (half ? g_t1l : g_t1h)
                         + ((size_t)((bm >> 4) + mt) * 64 + ks) * 128 + off;
        unsigned dst = (unsigned)__cvta_generic_to_shared(&sA[half * 512 + mt * 128 + off]);
        asm volatile("cp.async.cg.shared.global [%0], [%1], 16;" :: "r"(dst), "l"(src));
    }
    {   // B: 8 n-tiles x 64 floats x {hi,lo}
        int nt = r >> 4, off = (r & 15) * 4;
        const float* src = (half ? g_w4l : g_w4h)
                         + ((size_t)((bn >> 3) + nt) * 64 + ks) * 64 + off;
        unsigned dst = (unsigned)__cvta_generic_to_shared(&sB[half * 512 + nt * 64 + off]);
        asm volatile("cp.async.cg.shared.global [%0], [%1], 16;" :: "r"(dst), "l"(src));
    }
}

__global__ void __launch_bounds__(256) k2_core_gemm()
{
    __shared__ __align__(16) float sA[3][2048];
    __shared__ __align__(16) float sB[3][2048];

    const int tid  = threadIdx.x;
    const int lane = tid & 31;
    const int wid  = tid >> 5;
    const int wm   = wid >> 2;          // 0..1
    const int wn   = wid & 3;           // 0..3
    const int gid  = lane >> 2;
    const int tig  = lane & 3;
    const int bm   = blockIdx.x * 64;
    const int bn   = blockIdx.y * 64;

    float acc[2][2][4];
    #pragma unroll
    for (int mi = 0; mi < 2; mi++)
        #pragma unroll
        for (int ni = 0; ni < 2; ni++)
            #pragma unroll
            for (int r = 0; r < 4; r++) acc[mi][ni][r] = 0.f;

    #pragma unroll
    for (int st = 0; st < 2; st++) {
        k2_issue_slab(&sA[st][0],    &sB[st][0],    st * 2,     bm, bn, tid);
        k2_issue_slab(&sA[st][1024], &sB[st][1024], st * 2 + 1, bm, bn, tid);
        asm volatile("cp.async.commit_group;" ::: "memory");
    }

    int st = 0;
    for (int it = 0; it < 32; it++) {
        asm volatile("cp.async.wait_group 1;" ::: "memory");
        __syncthreads();
        #pragma unroll
        for (int s = 0; s < 2; s++) {
            uint4 ah[2], al[2];
            uint2 bh[2], bl[2];
            #pragma unroll
            for (int mi = 0; mi < 2; mi++) {
                ah[mi] = *(const uint4*)&sA[st][s * 1024 + (wm * 2 + mi) * 128 + lane * 4];
                al[mi] = *(const uint4*)&sA[st][s * 1024 + 512 + (wm * 2 + mi) * 128 + lane * 4];
            }
            #pragma unroll
            for (int ni = 0; ni < 2; ni++) {
                bh[ni] = *(const uint2*)&sB[st][s * 1024 + (wn * 2 + ni) * 64 + lane * 2];
                bl[ni] = *(const uint2*)&sB[st][s * 1024 + 512 + (wn * 2 + ni) * 64 + lane * 2];
            }
            if (s == 0) {
                if (it < 30) {
                    int nst = st + 2; if (nst >= 3) nst -= 3;
                    k2_issue_slab(&sA[nst][0],    &sB[nst][0],    (it + 2) * 2,     bm, bn, tid);
                    k2_issue_slab(&sA[nst][1024], &sB[nst][1024], (it + 2) * 2 + 1, bm, bn, tid);
                }
                asm volatile("cp.async.commit_group;" ::: "memory");
            }
            #pragma unroll
            for (int mi = 0; mi < 2; mi++)
                #pragma unroll
                for (int ni = 0; ni < 2; ni++) {
                    float* c = acc[mi][ni];
                    asm volatile(
                        "mma.sync.aligned.m16n8k8.row.col.f32.tf32.tf32.f32 "
                        "{%0,%1,%2,%3}, {%4,%5,%6,%7}, {%8,%9}, {%0,%1,%2,%3};"
                        : "+f"(c[0]), "+f"(c[1]), "+f"(c[2]), "+f"(c[3])
                        : "r"(ah[mi].x), "r"(ah[mi].y), "r"(ah[mi].z), "r"(ah[mi].w),
                          "r"(bh[ni].x), "r"(bh[ni].y));
                    asm volatile(
                        "mma.sync.aligned.m16n8k8.row.col.f32.tf32.tf32.f32 "
                        "{%0,%1,%2,%3}, {%4,%5,%6,%7}, {%8,%9}, {%0,%1,%2,%3};"
                        : "+f"(c[0]), "+f"(c[1]), "+f"(c[2]), "+f"(c[3])
                        : "r"(al[mi].x), "r"(al[mi].y), "r"(al[mi].z), "r"(al[mi].w),
                          "r"(bh[ni].x), "r"(bh[ni].y));
                    asm volatile(
                        "mma.sync.aligned.m16n8k8.row.col.f32.tf32.tf32.f32 "
                        "{%0,%1,%2,%3}, {%4,%5,%6,%7}, {%8,%9}, {%0,%1,%2,%3};"
                        : "+f"(c[0]), "+f"(c[1]), "+f"(c[2]), "+f"(c[3])
                        : "r"(ah[mi].x), "r"(ah[mi].y), "r"(ah[mi].z), "r"(ah[mi].w),
                          "r"(bl[ni].x), "r"(bl[ni].y));
                }
        }
        if (++st == 3) st = 0;
    }

    #pragma unroll
    for (int mi = 0; mi < 2; mi++)
        #pragma unroll
        for (int ni = 0; ni < 2; ni++) {
            int row0 = bm + wm * 32 + mi * 16 + gid;
            int col  = bn + wn * 16 + ni * 8 + tig * 2;
            float* c = acc[mi][ni];
            *(float2*)&g_u2[(size_t)row0 * RRR + col]       = make_float2(c[0], c[1]);
            *(float2*)&g_u2[(size_t)(row0 + 8) * RRR + col] = make_float2(c[2], c[3]);
        }
}

// ---------------------------------------------------------------------------
// Kernel 3: grid 2048 (ONE group per block; prologue amortized over 32 KB).
// Batch A (chunks 0-3) issues at entry and overlaps the prologue; batch B
// (chunks 4-7) issues right after the barrier and overlaps batch-A compute.
// f2 stays in smem (no reg hoist) to keep occupancy high.
// ---------------------------------------------------------------------------
__global__ void __launch_bounds__(256) k3_stream(
    const float* __restrict__ out_f2,
    const void*  __restrict__ maskp,
    float* __restrict__ out)
{
    __shared__ float f2t[RK * CC];   // f2t[Cr*128 + q]
    __shared__ float u2s[RRR];
    __shared__ float invw[MM];

    const int tid = threadIdx.x;
    const size_t g = blockIdx.x;

    // ---- batch A loads first (independent of smem; overlap prologue) ----
    const float4* sg = (const float4*)(g_s + g * TOK);
    float4 sa[4];
    #pragma unroll
    for (int it = 0; it < 4; it++)
        sa[it] = __ldcs(&sg[tid + it * 256]);

    // ---- prologue ----
    if (tid < 128)
        ((float4*)u2s)[tid] = ((const float4*)(g_u2 + g * RRR))[tid];
    #pragma unroll
    for (int i = tid; i < RK * CC; i += 256) {
        int q = i >> 3, Cr = i & 7;
        f2t[Cr * CC + q] = out_f2[i];
    }
    if (tid < 64) {
        int ge2 = g_flags[0], odd = g_flags[1];
        int w;
        if (ge2) {
            const float* mf = (const float*)maskp + g * 256;
            w = (mf[tid] != 0.f ? 0 : 1) + (mf[tid + 64] != 0.f ? 0 : 1)
              + (mf[tid + 128] != 0.f ? 0 : 1) + (mf[tid + 192] != 0.f ? 0 : 1);
        } else if (odd) {
            const unsigned char* mb = (const unsigned char*)maskp + g * 256;
            w = (mb[tid] ? 0 : 1) + (mb[tid + 64] ? 0 : 1)
              + (mb[tid + 128] ? 0 : 1) + (mb[tid + 192] ? 0 : 1);
        } else {
            const int* mi = (const int*)maskp + g * 256;
            w = (mi[tid] ? 0 : 1) + (mi[tid + 64] ? 0 : 1)
              + (mi[tid + 128] ? 0 : 1) + (mi[tid + 192] ? 0 : 1);
        }
        invw[tid] = (w > 0) ? 1.0f / ((float)w + 1e-10f) : 0.0f;
    }
    __syncthreads();

    // ---- batch B loads (overlap batch-A compute) ----
    float4 sb[4];
    #pragma unroll
    for (int it = 0; it < 4; it++)
        sb[it] = __ldcs(&sg[tid + 1024 + it * 256]);

    const int q0 = (tid & 31) << 2;
    float4* og = (float4*)(out + g * TOK);

    // ---- compute/store batch A (chunks 0-3) ----
    #pragma unroll
    for (int it = 0; it < 4; it++) {
        int i  = tid + it * 256;
        int m  = i >> 5;
        float r0 = 0.f, r1 = 0.f, r2 = 0.f, r3 = 0.f;
        #pragma unroll
        for (int Cr = 0; Cr < 8; Cr++) {
            float u = u2s[m * 8 + Cr];                      // warp-uniform
            float4 f = *(const float4*)&f2t[Cr * CC + q0];  // conflict-free
            r0 += u * f.x; r1 += u * f.y; r2 += u * f.z; r3 += u * f.w;
        }
        float iw = invw[m];
        float4 ov;
        ov.x = (r0 + sa[it].x) * iw;
        ov.y = (r1 + sa[it].y) * iw;
        ov.z = (r2 + sa[it].z) * iw;
        ov.w = (r3 + sa[it].w) * iw;
        __stcs(&og[i], ov);
    }
    // ---- compute/store batch B (chunks 4-7) ----
    #pragma unroll
    for (int it = 0; it < 4; it++) {
        int i  = tid + 1024 + it * 256;
        int m  = i >> 5;
        float r0 = 0.f, r1 = 0.f, r2 = 0.f, r3 = 0.f;
        #pragma unroll
        for (int Cr = 0; Cr < 8; Cr++) {
            float u = u2s[m * 8 + Cr];
            float4 f = *(const float4*)&f2t[Cr * CC + q0];
            r0 += u * f.x; r1 += u * f.y; r2 += u * f.z; r3 += u * f.w;
        }
        float iw = invw[m];
        float4 ov;
        ov.x = (r0 + sb[it].x) * iw;
        ov.y = (r1 + sb[it].y) * iw;
        ov.z = (r2 + sb[it].z) * iw;
        ov.w = (r3 + sb[it].w) * iw;
        __stcs(&og[i], ov);
    }
}

// ---------------------------------------------------------------------------
// inputs: 0:x 1:core 2:out_f0 3:out_f1 4:out_f2 5:in_f0 6:in_f1 7:in_f2 8:mask
// ---------------------------------------------------------------------------
extern "C" void kernel_launch(void* const* d_in, const int* in_sizes, int n_in,
                              void* d_out, int out_size)
{
    const float* x      = (const float*)d_in[0];
    const float* core   = (const float*)d_in[1];
    const float* out_f0 = (const float*)d_in[2];
    const float* out_f1 = (const float*)d_in[3];
    const float* out_f2 = (const float*)d_in[4];
    const float* in_f0  = (const float*)d_in[5];
    const float* in_f1  = (const float*)d_in[6];
    const float* in_f2  = (const float*)d_in[7];
    float* out = (float*)d_out;

    void* flags_ptr = nullptr;
    cudaGetSymbolAddress(&flags_ptr, g_flags);
    cudaMemsetAsync(flags_ptr, 0, 2 * sizeof(int));

    fold_and_scan<<<128, 256>>>(core, out_f0, out_f1, in_f0, in_f1,
                                (const unsigned char*)d_in[8]);
    k1_reduce_project<<<2 * GROUPS, 256>>>(x, in_f2);
    dim3 g2(GROUPS / 64, RRR / 64);
    k2_core_gemm<<<g2, 256>>>();
    k3_stream<<<GROUPS, 256>>>(out_f2, d_in[8], out);
}

// round 16
// speedup vs baseline: 1.0810x; 1.0148x over previous
#include <cuda_runtime.h>
#include <cstdint>

#define GROUPS  2048
#define MM      64
#define CC      128
#define TOK     8192
#define RK      8
#define RRR     512
#define MASKN   524288

// Fragment-permuted operand storage:
//  A (T1, 2048x512): tile (mt,ks), stored [mt][ks][128]; element (tr,tc)
//      at lane=(tr&7)*4+(tc&3), reg=(tr>>3)+((tc>>2)<<1)
//  B (W4, 512x512):  tile (nt,ks), stored [nt][ks][64];  element (n,k)
//      at lane=(n&7)*4+(k&3),  reg=k>>2
__device__ float g_s  [(size_t)GROUPS * TOK];  // 64 MB group sums
__device__ float g_t1h[(size_t)GROUPS * RRR];  // 4 MB  T1 hi (permuted)
__device__ float g_t1l[(size_t)GROUPS * RRR];  // 4 MB  T1 lo (permuted)
__device__ float g_u2 [(size_t)GROUPS * RRR];  // 4 MB
__device__ float g_w4h[RRR * RRR];             // 1 MB  W4 hi (permuted)
__device__ float g_w4l[RRR * RRR];             // 1 MB  W4 lo (permuted)
__device__ int   g_flags[2];                   // [ge2, odd]

__device__ __forceinline__ void tf32_split(float v, float& hi, float& lo)
{
    unsigned hb, lb;
    asm("cvt.rna.tf32.f32 %0, %1;" : "=r"(hb) : "f"(v));
    hi = __uint_as_float(hb);
    float r = v - hi;
    asm("cvt.rna.tf32.f32 %0, %1;" : "=r"(lb) : "f"(r));
    lo = __uint_as_float(lb);
}

__device__ __forceinline__ size_t a_perm_idx(int gr, int c)
{
    int mt = gr >> 4, tr = gr & 15;
    int ks = c >> 3,  tc = c & 7;
    int lane = (tr & 7) * 4 + (tc & 3);
    int reg  = (tr >> 3) + ((tc >> 2) << 1);
    return (size_t)(mt * 64 + ks) * 128 + lane * 4 + reg;
}
__device__ __forceinline__ size_t b_perm_idx(int n, int k)
{
    int nt = n >> 3, gid = n & 7;
    int ks = k >> 3, kc = k & 7;
    int lane = gid * 4 + (kc & 3);
    int reg  = kc >> 2;
    return (size_t)(nt * 64 + ks) * 64 + lane * 2 + reg;
}

// ---------------------------------------------------------------------------
// Combined fold + mask-scan kernel. blocks 0..63: fold W4; 64..127: scan mask.
// ---------------------------------------------------------------------------
__global__ void __launch_bounds__(256) fold_and_scan(
    const float* __restrict__ core,
    const float* __restrict__ of0, const float* __restrict__ of1,
    const float* __restrict__ if0, const float* __restrict__ if1,
    const unsigned char* __restrict__ mask)
{
    const int tid = threadIdx.x;

    if (blockIdx.x >= 64) {
        // ---- mask dtype scan (64 blocks) ----
        const uint4* p = (const uint4*)mask;
        unsigned acc = 0;
        int i = (blockIdx.x - 64) * 256 + tid;
        for (; i < MASKN / 16; i += 64 * 256) {
            uint4 v = p[i];
            acc |= (v.x | v.y | v.z | v.w);
        }
        __shared__ unsigned sacc;
        if (tid == 0) sacc = 0;
        __syncthreads();
        #pragma unroll
        for (int off = 16; off >= 1; off >>= 1)
            acc |= __shfl_xor_sync(0xffffffffu, acc, off);
        if ((tid & 31) == 0) atomicOr(&sacc, acc);
        __syncthreads();
        if (tid == 0) {
            unsigned a = sacc;
            if (a & 0xFEFEFEFEu) atomicOr(&g_flags[0], 1);
            if (a & 0xFFFFFF00u) atomicOr(&g_flags[1], 1);
        }
        return;
    }

    // ---- fold (64 blocks), one (C,F) pair per block ----
    __shared__ float bufA[4096], bufB[4096];
    __shared__ float sf[4][64];
    const int C = blockIdx.x >> 3, F = blockIdx.x & 7;

    if (tid < 64)       sf[0][tid]       = of0[tid];
    else if (tid < 128) sf[1][tid - 64]  = of1[tid - 64];
    else if (tid < 192) sf[2][tid - 128] = if0[tid - 128];
    else                sf[3][tid - 192] = if1[tid - 192];

    #pragma unroll
    for (int i = tid; i < 4096; i += 256) {
        int A = i >> 9, B = (i >> 6) & 7, D = (i >> 3) & 7, E = i & 7;
        bufA[i] = core[A * 32768 + B * 4096 + C * 512 + D * 64 + E * 8 + F];
    }
    __syncthreads();
    #pragma unroll
    for (int i = tid; i < 4096; i += 256) {   // M1[A,B,D,d] = sum_E K * if1[d,E]
        int ABD = i >> 3, d = i & 7;
        float acc = 0.f;
        #pragma unroll
        for (int E = 0; E < 8; E++) acc += bufA[ABD * 8 + E] * sf[3][d * 8 + E];
        bufB[i] = acc;
    }
    __syncthreads();
    #pragma unroll
    for (int i = tid; i < 4096; i += 256) {   // M2[A,B,d,a] = sum_D M1 * if0[a,D]
        int AB = i >> 6, d = (i >> 3) & 7, a = i & 7;
        float acc = 0.f;
        #pragma unroll
        for (int D = 0; D < 8; D++) acc += bufB[(AB * 8 + D) * 8 + d] * sf[2][a * 8 + D];
        bufA[i] = acc;
    }
    __syncthreads();
    #pragma unroll
    for (int i = tid; i < 4096; i += 256) {   // M3[B,d,a,o] = sum_A M2 * of0[o,A]
        int B = i >> 9, d = (i >> 6) & 7, a = (i >> 3) & 7, o = i & 7;
        float acc = 0.f;
        #pragma unroll
        for (int A = 0; A < 8; A++)
            acc += bufA[((A * 8 + B) * 8 + d) * 8 + a] * sf[0][o * 8 + A];
        bufB[i] = acc;
    }
    __syncthreads();
    #pragma unroll
    for (int i = tid; i < 4096; i += 256) {   // W4 = sum_B M3 * of1[p,B]
        int o = i >> 9, p = (i >> 6) & 7, a = (i >> 3) & 7, d = i & 7;
        float acc = 0.f;
        #pragma unroll
        for (int B = 0; B < 8; B++)
            acc += bufB[((B * 8 + d) * 8 + a) * 8 + o] * sf[1][p * 8 + B];
        float hi, lo;
        tf32_split(acc, hi, lo);
        int n = (o * 8 + p) * 8 + C;
        int k = a * 64 + d * 8 + F;
        size_t idx = b_perm_idx(n, k);
        g_w4h[idx] = hi;
        g_w4l[idx] = lo;
    }
}

// ---------------------------------------------------------------------------
// Kernel 1: grid 4096 (half-group per block): s -> scratch, T1 hi/lo permuted.
// ALL 16 LDG.128 issue at kernel entry (MLP=16/thread); the f2q staging
// overlaps DRAM latency; reduce/store then consumes landed registers.
// ---------------------------------------------------------------------------
__global__ void __launch_bounds__(256) k1_reduce_project(
    const float* __restrict__ x,
    const float* __restrict__ in_f2)   // (128,8)
{
    __shared__ __align__(16) float s[32 * 132];
    __shared__ __align__(16) float f2q[8 * 132];   // [F][e]
    __shared__ __align__(16) float part[32 * 68];  // p[m][c][F] = m*68+c*8+F

    const int tid = threadIdx.x;
    const int g = blockIdx.x >> 1, h = blockIdx.x & 1;
    const size_t base = (size_t)g * (4 * TOK) + h * 4096;

    // ---- all 16 streaming loads first ----
    const float4* xb = (const float4*)(x + base);
    float4 v[16];
    #pragma unroll
    for (int it = 0; it < 4; it++) {
        int i = tid + it * 256;
        v[it * 4 + 0] = __ldcs(&xb[i]);
        v[it * 4 + 1] = __ldcs(&xb[i + 2048]);
        v[it * 4 + 2] = __ldcs(&xb[i + 4096]);
        v[it * 4 + 3] = __ldcs(&xb[i + 6144]);
    }

    // ---- overlaps the loads above ----
    #pragma unroll
    for (int i = tid; i < CC * RK; i += 256) {
        int e = i >> 3, F = i & 7;
        f2q[F * 132 + e] = in_f2[i];
    }

    float4* sg = (float4*)(g_s + (size_t)g * TOK + h * 4096);
    #pragma unroll
    for (int it = 0; it < 4; it++) {
        int i = tid + it * 256;
        float4 v0 = v[it * 4 + 0], v1 = v[it * 4 + 1];
        float4 v2 = v[it * 4 + 2], v3 = v[it * 4 + 3];
        float4 r;
        r.x = (v0.x + v1.x) + (v2.x + v3.x);
        r.y = (v0.y + v1.y) + (v2.y + v3.y);
        r.z = (v0.z + v1.z) + (v2.z + v3.z);
        r.w = (v0.w + v1.w) + (v2.w + v3.w);
        sg[i] = r;
        int m = i >> 5;
        int e = (i & 31) << 2;
        *(float4*)&s[m * 132 + e] = r;
    }
    __syncthreads();

    // phase 2a: partials. m = tid&31 (lane), c = tid>>5 (warp-uniform chunk)
    {
        int m = tid & 31;
        int c = tid >> 5;
        const float4* s4 = (const float4*)&s[m * 132 + c * 16];
        float acc[8];
        #pragma unroll
        for (int F = 0; F < 8; F++) acc[F] = 0.f;
        #pragma unroll
        for (int q = 0; q < 4; q++) {
            float4 a = s4[q];                       // row read, conflict-free
            #pragma unroll
            for (int F = 0; F < 8; F++) {
                float4 b = *(const float4*)&f2q[F * 132 + c * 16 + q * 4]; // broadcast
                acc[F] += a.x * b.x + a.y * b.y + a.z * b.z + a.w * b.w;
            }
        }
        #pragma unroll
        for (int F = 0; F < 8; F += 4)
            *(float4*)&part[m * 68 + c * 8 + F] = make_float4(acc[F], acc[F+1], acc[F+2], acc[F+3]);
    }
    __syncthreads();

    // phase 2b: reduce 8 chunks -> t1[m,F], tf32-split, permuted store
    {
        int m = tid >> 3, F = tid & 7;
        float acc = 0.f;
        #pragma unroll
        for (int c = 0; c < 8; c++)
            acc += part[m * 68 + c * 8 + F];
        float hi, lo;
        tf32_split(acc, hi, lo);
        size_t idx = a_perm_idx(g, (h * 32 + m) * 8 + F);
        g_t1h[idx] = hi;
        g_t1l[idx] = lo;
    }
}

// ---------------------------------------------------------------------------
// Kernel 2: U2 = T1 @ W4^T — cp.async 3-stage pipeline, BK=64 (2 k8-slabs per
// stage), ONE __syncthreads per iteration. BM=64 BN=64, 3xTF32, grid (32,8).
// ---------------------------------------------------------------------------
__device__ __forceinline__ void k2_issue_slab(float* sA, float* sB, int ks,
                                              int bm, int bn, int tid)
{
    int half = tid >> 7, r = tid & 127;
    {   // A: 4 m-tiles x 128 floats x {hi,lo}
        int mt = r >> 5, off = (r & 31) * 4;
        const float* src = (half ? g_t1l : g_t1h)
                         + ((size_t)((bm >> 4) + mt) * 64 + ks) * 128 + off;
        unsigned dst = (unsigned)__cvta_generic_to_shared(&sA[half * 512 + mt * 128 + off]);
        asm volatile("cp.async.cg.shared.global [%0], [%1], 16;" :: "r"(dst), "l"(src));
    }
    {   // B: 8 n-tiles x 64 floats x {hi,lo}
        int nt = r >> 4, off = (r & 15) * 4;
        const float* src = (half ? g_w4l : g_w4h)
                         + ((size_t)((bn >> 3) + nt) * 64 + ks) * 64 + off;
        unsigned dst = (unsigned)__cvta_generic_to_shared(&sB[half * 512 + nt * 64 + off]);
        asm volatile("cp.async.cg.shared.global [%0], [%1], 16;" :: "r"(dst), "l"(src));
    }
}

__global__ void __launch_bounds__(256) k2_core_gemm()
{
    __shared__ __align__(16) float sA[3][2048];
    __shared__ __align__(16) float sB[3][2048];

    const int tid  = threadIdx.x;
    const int lane = tid & 31;
    const int wid  = tid >> 5;
    const int wm   = wid >> 2;          // 0..1
    const int wn   = wid & 3;           // 0..3
    const int gid  = lane >> 2;
    const int tig  = lane & 3;
    const int bm   = blockIdx.x * 64;
    const int bn   = blockIdx.y * 64;

    float acc[2][2][4];
    #pragma unroll
    for (int mi = 0; mi < 2; mi++)
        #pragma unroll
        for (int ni = 0; ni < 2; ni++)
            #pragma unroll
            for (int r = 0; r < 4; r++) acc[mi][ni][r] = 0.f;

    #pragma unroll
    for (int st = 0; st < 2; st++) {
        k2_issue_slab(&sA[st][0],    &sB[st][0],    st * 2,     bm, bn, tid);
        k2_issue_slab(&sA[st][1024], &sB[st][1024], st * 2 + 1, bm, bn, tid);
        asm volatile("cp.async.commit_group;" ::: "memory");
    }

    int st = 0;
    for (int it = 0; it < 32; it++) {
        asm volatile("cp.async.wait_group 1;" ::: "memory");
        __syncthreads();
        #pragma unroll
        for (int s = 0; s < 2; s++) {
            uint4 ah[2], al[2];
            uint2 bh[2], bl[2];
            #pragma unroll
            for (int mi = 0; mi < 2; mi++) {
                ah[mi] = *(const uint4*)&sA[st][s * 1024 + (wm * 2 + mi) * 128 + lane * 4];
                al[mi] = *(const uint4*)&sA[st][s * 1024 + 512 + (wm * 2 + mi) * 128 + lane * 4];
            }
            #pragma unroll
            for (int ni = 0; ni < 2; ni++) {
                bh[ni] = *(const uint2*)&sB[st][s * 1024 + (wn * 2 + ni) * 64 + lane * 2];
                bl[ni] = *(const uint2*)&sB[st][s * 1024 + 512 + (wn * 2 + ni) * 64 + lane * 2];
            }
            if (s == 0) {
                if (it < 30) {
                    int nst = st + 2; if (nst >= 3) nst -= 3;
                    k2_issue_slab(&sA[nst][0],    &sB[nst][0],    (it + 2) * 2,     bm, bn, tid);
                    k2_issue_slab(&sA[nst][1024], &sB[nst][1024], (it + 2) * 2 + 1, bm, bn, tid);
                }
                asm volatile("cp.async.commit_group;" ::: "memory");
            }
            #pragma unroll
            for (int mi = 0; mi < 2; mi++)
                #pragma unroll
                for (int ni = 0; ni < 2; ni++) {
                    float* c = acc[mi][ni];
                    asm volatile(
                        "mma.sync.aligned.m16n8k8.row.col.f32.tf32.tf32.f32 "
                        "{%0,%1,%2,%3}, {%4,%5,%6,%7}, {%8,%9}, {%0,%1,%2,%3};"
                        : "+f"(c[0]), "+f"(c[1]), "+f"(c[2]), "+f"(c[3])
                        : "r"(ah[mi].x), "r"(ah[mi].y), "r"(ah[mi].z), "r"(ah[mi].w),
                          "r"(bh[ni].x), "r"(bh[ni].y));
                    asm volatile(
                        "mma.sync.aligned.m16n8k8.row.col.f32.tf32.tf32.f32 "
                        "{%0,%1,%2,%3}, {%4,%5,%6,%7}, {%8,%9}, {%0,%1,%2,%3};"
                        : "+f"(c[0]), "+f"(c[1]), "+f"(c[2]), "+f"(c[3])
                        : "r"(al[mi].x), "r"(al[mi].y), "r"(al[mi].z), "r"(al[mi].w),
                          "r"(bh[ni].x), "r"(bh[ni].y));
                    asm volatile(
                        "mma.sync.aligned.m16n8k8.row.col.f32.tf32.tf32.f32 "
                        "{%0,%1,%2,%3}, {%4,%5,%6,%7}, {%8,%9}, {%0,%1,%2,%3};"
                        : "+f"(c[0]), "+f"(c[1]), "+f"(c[2]), "+f"(c[3])
                        : "r"(ah[mi].x), "r"(ah[mi].y), "r"(ah[mi].z), "r"(ah[mi].w),
                          "r"(bl[ni].x), "r"(bl[ni].y));
                }
        }
        if (++st == 3) st = 0;
    }

    #pragma unroll
    for (int mi = 0; mi < 2; mi++)
        #pragma unroll
        for (int ni = 0; ni < 2; ni++) {
            int row0 = bm + wm * 32 + mi * 16 + gid;
            int col  = bn + wn * 16 + ni * 8 + tig * 2;
            float* c = acc[mi][ni];
            *(float2*)&g_u2[(size_t)row0 * RRR + col]       = make_float2(c[0], c[1]);
            *(float2*)&g_u2[(size_t)(row0 + 8) * RRR + col] = make_float2(c[2], c[3]);
        }
}

// ---------------------------------------------------------------------------
// Kernel 3: grid 2048 (one group per block). Two-batch load pipeline.
// ---------------------------------------------------------------------------
__global__ void __launch_bounds__(256) k3_stream(
    const float* __restrict__ out_f2,
    const void*  __restrict__ maskp,
    float* __restrict__ out)
{
    __shared__ float f2t[RK * CC];   // f2t[Cr*128 + q]
    __shared__ float u2s[RRR];
    __shared__ float invw[MM];

    const int tid = threadIdx.x;
    const size_t g = blockIdx.x;

    // ---- batch A loads first (independent of smem; overlap prologue) ----
    const float4* sg = (const float4*)(g_s + g * TOK);
    float4 sa[4];
    #pragma unroll
    for (int it = 0; it < 4; it++)
        sa[it] = __ldcs(&sg[tid + it * 256]);

    // ---- prologue ----
    if (tid < 128)
        ((float4*)u2s)[tid] = ((const float4*)(g_u2 + g * RRR))[tid];
    #pragma unroll
    for (int i = tid; i < RK * CC; i += 256) {
        int q = i >> 3, Cr = i & 7;
        f2t[Cr * CC + q] = out_f2[i];
    }
    if (tid < 64) {
        int ge2 = g_flags[0], odd = g_flags[1];
        int w;
        if (ge2) {
            const float* mf = (const float*)maskp + g * 256;
            w = (mf[tid] != 0.f ? 0 : 1) + (mf[tid + 64] != 0.f ? 0 : 1)
              + (mf[tid + 128] != 0.f ? 0 : 1) + (mf[tid + 192] != 0.f ? 0 : 1);
        } else if (odd) {
            const unsigned char* mb = (const unsigned char*)maskp + g * 256;
            w = (mb[tid] ? 0 : 1) + (mb[tid + 64] ? 0 : 1)
              + (mb[tid + 128] ? 0 : 1) + (mb[tid + 192] ? 0 : 1);
        } else {
            const int* mi = (const int*)maskp + g * 256;
            w = (mi[tid] ? 0 : 1) + (mi[tid + 64] ? 0 : 1)
              + (mi[tid + 128] ? 0 : 1) + (mi[tid + 192] ? 0 : 1);
        }
        invw[tid] = (w > 0) ? 1.0f / ((float)w + 1e-10f) : 0.0f;
    }
    __syncthreads();

    // ---- batch B loads (overlap batch-A compute) ----
    float4 sb[4];
    #pragma unroll
    for (int it = 0; it < 4; it++)
        sb[it] = __ldcs(&sg[tid + 1024 + it * 256]);

    const int q0 = (tid & 31) << 2;
    float4* og = (float4*)(out + g * TOK);

    // ---- compute/store batch A (chunks 0-3) ----
    #pragma unroll
    for (int it = 0; it < 4; it++) {
        int i  = tid + it * 256;
        int m  = i >> 5;
        float r0 = 0.f, r1 = 0.f, r2 = 0.f, r3 = 0.f;
        #pragma unroll
        for (int Cr = 0; Cr < 8; Cr++) {
            float u = u2s[m * 8 + Cr];                      // warp-uniform
            float4 f = *(const float4*)&f2t[Cr * CC + q0];  // conflict-free
            r0 += u * f.x; r1 += u * f.y; r2 += u * f.z; r3 += u * f.w;
        }
        float iw = invw[m];
        float4 ov;
        ov.x = (r0 + sa[it].x) * iw;
        ov.y = (r1 + sa[it].y) * iw;
        ov.z = (r2 + sa[it].z) * iw;
        ov.w = (r3 + sa[it].w) * iw;
        __stcs(&og[i], ov);
    }
    // ---- compute/store batch B (chunks 4-7) ----
    #pragma unroll
    for (int it = 0; it < 4; it++) {
        int i  = tid + 1024 + it * 256;
        int m  = i >> 5;
        float r0 = 0.f, r1 = 0.f, r2 = 0.f, r3 = 0.f;
        #pragma unroll
        for (int Cr = 0; Cr < 8; Cr++) {
            float u = u2s[m * 8 + Cr];
            float4 f = *(const float4*)&f2t[Cr * CC + q0];
            r0 += u * f.x; r1 += u * f.y; r2 += u * f.z; r3 += u * f.w;
        }
        float iw = invw[m];
        float4 ov;
        ov.x = (r0 + sb[it].x) * iw;
        ov.y = (r1 + sb[it].y) * iw;
        ov.z = (r2 + sb[it].z) * iw;
        ov.w = (r3 + sb[it].w) * iw;
        __stcs(&og[i], ov);
    }
}

// ---------------------------------------------------------------------------
// inputs: 0:x 1:core 2:out_f0 3:out_f1 4:out_f2 5:in_f0 6:in_f1 7:in_f2 8:mask
// ---------------------------------------------------------------------------
extern "C" void kernel_launch(void* const* d_in, const int* in_sizes, int n_in,
                              void* d_out, int out_size)
{
    const float* x      = (const float*)d_in[0];
    const float* core   = (const float*)d_in[1];
    const float* out_f0 = (const float*)d_in[2];
    const float* out_f1 = (const float*)d_in[3];
    const float* out_f2 = (const float*)d_in[4];
    const float* in_f0  = (const float*)d_in[5];
    const float* in_f1  = (const float*)d_in[6];
    const float* in_f2  = (const float*)d_in[7];
    float* out = (float*)d_out;

    void* flags_ptr = nullptr;
    cudaGetSymbolAddress(&flags_ptr, g_flags);
    cudaMemsetAsync(flags_ptr, 0, 2 * sizeof(int));

    fold_and_scan<<<128, 256>>>(core, out_f0, out_f1, in_f0, in_f1,
                                (const unsigned char*)d_in[8]);
    k1_reduce_project<<<2 * GROUPS, 256>>>(x, in_f2);
    dim3 g2(GROUPS / 64, RRR / 64);
    k2_core_gemm<<<g2, 256>>>();
    k3_stream<<<GROUPS, 256>>>(out_f2, d_in[8], out);
}